// round 10
// baseline (speedup 1.0000x reference)
#include <cuda_runtime.h>

// ---------------------------------------------------------------------------
// Contourlet dfbrec4 reconstruction.
//   Stage 1: fbrec('2c','per')      on (8,64,128,128) -> X (8,64,128,256)
//   Stage 2: fbrec('1r','qper_col') on (8,32,128,256) -> out (8,32,256,256)
// ---------------------------------------------------------------------------

#define ISQ2 0.70710678118654752440f
#define SQ2  1.41421356237309504880f

// dfb filter taps as function-local constexpr -> FFMA immediates.
#define DECLARE_FILT() \
    constexpr float FILT[12] = { \
         0.0144f,  0.0272f,  0.0526f,  0.0972f,  0.193f,   0.63f, \
        -0.63f,   -0.193f,  -0.0972f, -0.0526f, -0.0272f, -0.0144f }

// Scratch (allocation-free rule: __device__ globals)
__device__ float g_p1[8 * 64 * 128 * 128];   // 32 MB
__device__ float g_p0[8 * 64 * 128 * 128];   // 32 MB
__device__ float g_X [8 * 64 * 128 * 256];   // 64 MB
__device__ float g_q1[8 * 32 * 128 * 256];   // 32 MB
__device__ float g_q0[8 * 32 * 128 * 256];   // 32 MB

#define EXT_S 84   // ext row stride (floats): mult of 4, 84 mod 32 = 20 -> vec conflict-free
#define TMP_S 68   // tmp row stride: mult of 4, 68 mod 32 = 4 -> vec conflict-free

// ---------------------------------------------------------------------------
// Separable 12-tap conv, 32x64 output tile, block = 256 threads (8 warps).
// halo -> smem(ext), H-pass via LDS.128 sliding window -> smem(tmp, STS.128),
// V-pass via column-pair LDS.64 -> float2 acc[4] (thread = 2 cols x 4 rows).
// Row wrap periodic mod 128; on wrap, column shifted by HSHIFT ('qper_col').
// ---------------------------------------------------------------------------
template <int W, int HSHIFT, int RC>
__device__ __forceinline__ void conv32x64(const float* __restrict__ plane,
                                          int r0, int c0,
                                          float* __restrict__ ext,   // 43*EXT_S
                                          float* __restrict__ tmp,   // 43*TMP_S
                                          float2 acc[4])
{
    DECLARE_FILT();
    const int tid  = threadIdx.x;
    const int lane = tid & 31;
    const int warp = tid >> 5;

    // ---- halo load: 43 rows x 75 cols; warp = row stripe, lane = col ----
    for (int er = warp; er < 43; er += 8) {
        int gr = r0 + er - RC;
        int cs = 0;
        if (gr < 0)        { gr += 128; cs = HSHIFT; }
        else if (gr >= 128){ gr -= 128; cs = HSHIFT; }
        const float* rowp = plane + gr * W;
        const int base = c0 - RC + cs;
        float* erow = ext + er * EXT_S;
        #pragma unroll
        for (int ec0 = 0; ec0 < 96; ec0 += 32) {
            int ec = ec0 + lane;
            if (ec < 75)
                erow[ec] = __ldg(rowp + ((base + ec) & (W - 1)));
        }
    }
    __syncthreads();

    // ---- horizontal pass: warp = 8-col strip, lane(+32) = row ----
    // 5 LDS.128 -> 19-value window -> 8 outputs -> 2 STS.128.
    {
        const int sb = warp << 3;
        #pragma unroll
        for (int half = 0; half < 2; half++) {
            int er = lane + half * 32;
            if (er < 43) {
                const float4* src = (const float4*)(ext + er * EXT_S + sb);
                float xx[20];
                #pragma unroll
                for (int q = 0; q < 5; q++) {
                    float4 v = src[q];
                    xx[4*q] = v.x; xx[4*q+1] = v.y; xx[4*q+2] = v.z; xx[4*q+3] = v.w;
                }
                float a[8] = {0.f,0.f,0.f,0.f,0.f,0.f,0.f,0.f};
                #pragma unroll
                for (int u = 0; u < 19; u++) {
                    #pragma unroll
                    for (int ss = 0; ss < 8; ss++) {
                        int k = u - ss;
                        if (k >= 0 && k < 12) a[ss] = fmaf(FILT[k], xx[u], a[ss]);
                    }
                }
                float4* dst = (float4*)(tmp + er * TMP_S + sb);
                dst[0] = make_float4(a[0], a[1], a[2], a[3]);
                dst[1] = make_float4(a[4], a[5], a[6], a[7]);
            }
        }
    }
    __syncthreads();

    // ---- vertical pass: thread = (col pair cp, 4-row strip rsb) ----
    const int cp  = tid & 31;
    const int rsb = tid >> 5;
    const float2* colp = (const float2*)tmp + rsb * (2 * TMP_S) + cp;
    #pragma unroll
    for (int ss = 0; ss < 4; ss++) { acc[ss].x = 0.f; acc[ss].y = 0.f; }
    #pragma unroll
    for (int u = 0; u < 15; u++) {
        float2 w = colp[u * (TMP_S / 2)];
        #pragma unroll
        for (int ss = 0; ss < 4; ss++) {
            int k = u - ss;
            if (k >= 0 && k < 12) {
                acc[ss].x = fmaf(FILT[k], w.x, acc[ss].x);
                acc[ss].y = fmaf(FILT[k], w.y, acc[ss].y);
            }
        }
    }
}

// ---------------------------------------------------------------------------
// Stage 1, step 1:  p1 = -isq2 * (Y1 + sep12(Y0, per, shift(0,0)))
//   Y0 = concat(y1, y2) on channels; Y1 = concat(y0, y3).
// grid (2, 4, 512)
// ---------------------------------------------------------------------------
__global__ __launch_bounds__(256) void k_p1(const float* __restrict__ y0,
                                            const float* __restrict__ y1,
                                            const float* __restrict__ y2,
                                            const float* __restrict__ y3)
{
    __shared__ float ext[43 * EXT_S];
    __shared__ float tmp[43 * TMP_S];
    const int z  = blockIdx.z;
    const int b  = z >> 6;
    const int ch = z & 63;
    const int half = (b << 5) + (ch & 31);
    const float* convp = (ch < 32 ? y1 : y2) + half * 16384;
    const float* combp = (ch < 32 ? y0 : y3) + half * 16384;
    float*       outp  = g_p1 + z * 16384;

    const int r0 = blockIdx.y << 5, c0 = blockIdx.x << 6;
    float2 acc[4];
    conv32x64<128, 0, 5>(convp, r0, c0, ext, tmp, acc);

    const int cp = threadIdx.x & 31, rsb = threadIdx.x >> 5;
    int base = (r0 + rsb * 4) * 128 + c0 + 2 * cp;
    #pragma unroll
    for (int i = 0; i < 4; i++, base += 128) {
        float2 cb = *(const float2*)(combp + base);
        float2 o;
        o.x = -ISQ2 * (cb.x + acc[i].x);
        o.y = -ISQ2 * (cb.y + acc[i].y);
        *(float2*)(outp + base) = o;
    }
}

// ---------------------------------------------------------------------------
// Stage 1, step 2:  p0 = sq2 * Y0 + sep12(p1, per, shift(1,1))
// ---------------------------------------------------------------------------
__global__ __launch_bounds__(256) void k_p0(const float* __restrict__ y1,
                                            const float* __restrict__ y2)
{
    __shared__ float ext[43 * EXT_S];
    __shared__ float tmp[43 * TMP_S];
    const int z  = blockIdx.z;
    const int b  = z >> 6;
    const int ch = z & 63;
    const int half = (b << 5) + (ch & 31);
    const float* convp = g_p1 + z * 16384;
    const float* combp = (ch < 32 ? y1 : y2) + half * 16384;
    float*       outp  = g_p0 + z * 16384;

    const int r0 = blockIdx.y << 5, c0 = blockIdx.x << 6;
    float2 acc[4];
    conv32x64<128, 0, 6>(convp, r0, c0, ext, tmp, acc);

    const int cp = threadIdx.x & 31, rsb = threadIdx.x >> 5;
    int base = (r0 + rsb * 4) * 128 + c0 + 2 * cp;
    #pragma unroll
    for (int i = 0; i < 4; i++, base += 128) {
        float2 cb = *(const float2*)(combp + base);
        float2 o;
        o.x = SQ2 * cb.x + acc[i].x;
        o.y = SQ2 * cb.y + acc[i].y;
        *(float2*)(outp + base) = o;
    }
}

// ---------------------------------------------------------------------------
// qprec '2c' (smem-staged, vectorized):
//   X[z][i][j], zc=(i+j) mod 256, t=zc>>1
//     even: X = p0[((i-j)/2)&127][((i+j)>>1)&127]
//     odd : X = p1[((i-j-1)/2)&127][((i+j-1)>>1)&127]
// Load: float4 (T0 mult of 32 -> aligned; col (T0+4l)&127 stays 4-aligned).
// Gather: dj-pairs, di warp-uniform -> no divergence, STG.64.
// grid (4, 2, 512), block 256
// ---------------------------------------------------------------------------
__global__ __launch_bounds__(256) void k_qprec2c()
{
    __shared__ float sm[2 * 64 * 64];
    const int z  = blockIdx.z;
    const int i0 = blockIdx.y << 6;
    const int j0 = blockIdx.x << 6;
    const float* p0 = g_p0 + z * 16384;
    const float* p1 = g_p1 + z * 16384;

    const int T0  = ((i0 + j0) >> 1) & 127;
    const int ihj = (i0 - j0) >> 1;
    const int D0  = (ihj - 31) & 127;        // sm0 row base
    const int D1  = (ihj - 32) & 127;        // sm1 row base

    const int l  = threadIdx.x & 15;
    const int u0 = threadIdx.x >> 4;
    #pragma unroll
    for (int it = 0; it < 4; it++) {
        int v   = u0 + it * 16;
        int col = (T0 + 4 * l) & 127;
        float4 a = *(const float4*)(p0 + (((D0 + v) & 127) << 7) + col);
        float4 b = *(const float4*)(p1 + (((D1 + v) & 127) << 7) + col);
        *(float4*)(sm + v * 64 + 4 * l)        = a;
        *(float4*)(sm + 4096 + v * 64 + 4 * l) = b;
    }
    __syncthreads();

    float* Xp = g_X + z * 32768;
    const int p = threadIdx.x & 31;
    #pragma unroll
    for (int it = 0; it < 8; it++) {
        int di = it * 8 + (threadIdx.x >> 5);   // warp-uniform
        int d2 = di >> 1;
        float2 o;
        if (di & 1) {
            o.x = sm[4096 + (d2 - p + 32) * 64 + (d2 + p)];
            o.y = sm[(d2 - p + 31) * 64 + (d2 + p + 1)];
        } else {
            int off = (d2 - p + 31) * 64 + (d2 + p);
            o.x = sm[off];
            o.y = sm[4096 + off];
        }
        *(float2*)(Xp + (i0 + di) * 256 + j0 + 2 * p) = o;
    }
}

// ---------------------------------------------------------------------------
// Stage 2, step 1:  q1 = -isq2 * (x1 + sep12(x0, qper_col, shift(0,0)))
//   x0 = X[:, :32], x1 = X[:, 32:].  W = 256, half-shift = 128.
// grid (4, 4, 256)
// ---------------------------------------------------------------------------
__global__ __launch_bounds__(256) void k_q1()
{
    __shared__ float ext[43 * EXT_S];
    __shared__ float tmp[43 * TMP_S];
    const int z  = blockIdx.z;
    const int b  = z >> 5;
    const int ch = z & 31;
    const float* convp = g_X + (b * 64 + ch) * 32768;
    const float* combp = g_X + (b * 64 + 32 + ch) * 32768;
    float*       outp  = g_q1 + z * 32768;

    const int r0 = blockIdx.y << 5, c0 = blockIdx.x << 6;
    float2 acc[4];
    conv32x64<256, 128, 5>(convp, r0, c0, ext, tmp, acc);

    const int cp = threadIdx.x & 31, rsb = threadIdx.x >> 5;
    int base = (r0 + rsb * 4) * 256 + c0 + 2 * cp;
    #pragma unroll
    for (int i = 0; i < 4; i++, base += 256) {
        float2 cb = *(const float2*)(combp + base);
        float2 o;
        o.x = -ISQ2 * (cb.x + acc[i].x);
        o.y = -ISQ2 * (cb.y + acc[i].y);
        *(float2*)(outp + base) = o;
    }
}

// ---------------------------------------------------------------------------
// Stage 2, step 2:  q0 = sq2 * x0 + sep12(q1, qper_col, shift(1,1))
// ---------------------------------------------------------------------------
__global__ __launch_bounds__(256) void k_q0()
{
    __shared__ float ext[43 * EXT_S];
    __shared__ float tmp[43 * TMP_S];
    const int z  = blockIdx.z;
    const int b  = z >> 5;
    const int ch = z & 31;
    const float* convp = g_q1 + z * 32768;
    const float* combp = g_X + (b * 64 + ch) * 32768;
    float*       outp  = g_q0 + z * 32768;

    const int r0 = blockIdx.y << 5, c0 = blockIdx.x << 6;
    float2 acc[4];
    conv32x64<256, 128, 6>(convp, r0, c0, ext, tmp, acc);

    const int cp = threadIdx.x & 31, rsb = threadIdx.x >> 5;
    int base = (r0 + rsb * 4) * 256 + c0 + 2 * cp;
    #pragma unroll
    for (int i = 0; i < 4; i++, base += 256) {
        float2 cb = *(const float2*)(combp + base);
        float2 o;
        o.x = SQ2 * cb.x + acc[i].x;
        o.y = SQ2 * cb.y + acc[i].y;
        *(float2*)(outp + base) = o;
    }
}

// ---------------------------------------------------------------------------
// qprec '1r' (smem-staged, vectorized, wrap-correct):
//   out[z][io][j]: zr = (io+j) mod 256, t = zr>>1
//     even: out = q0[t][(j-t)&255];  odd: out = q1[t][(j-1-t)&255]
// Staged row u holds cols (chb-32+w128(u) + l)&255, l in [0,64); base mult of
// 32 -> float4 loads. w128(u) = 128*(S0+2u >= 256) handles the mod-256 wrap.
// Gather (l offsets re-derived for the -32 base):
//   even s: l = (dj-dio)/2   + 32;  odd s: l = (dj-dio-1)/2 + 32.
// grid (4, 4, 256), block 256
// ---------------------------------------------------------------------------
__global__ __launch_bounds__(256) void k_qprec1r(float* __restrict__ out)
{
    __shared__ float sm[2 * 64 * 64];
    const int z   = blockIdx.z;
    const int io0 = blockIdx.y << 6;
    const int j0  = blockIdx.x << 6;
    const float* q0 = g_q0 + z * 32768;
    const float* q1 = g_q1 + z * 32768;

    const int S0  = io0 + j0;
    const int T0  = (S0 >> 1) & 127;
    const int chb = (j0 - io0) >> 1;

    const int l  = threadIdx.x & 15;
    const int u0 = threadIdx.x >> 4;
    #pragma unroll
    for (int it = 0; it < 4; it++) {
        int u    = u0 + it * 16;
        int row  = ((T0 + u) & 127) << 8;
        int w128 = (S0 + 2 * u >= 256) ? 128 : 0;
        int col  = (chb - 32 + w128 + 4 * l) & 255;
        float4 a = *(const float4*)(q0 + row + col);
        float4 b = *(const float4*)(q1 + row + col);
        *(float4*)(sm + u * 64 + 4 * l)        = a;
        *(float4*)(sm + 4096 + u * 64 + 4 * l) = b;
    }
    __syncthreads();

    float* op = out + z * 65536;
    const int p = threadIdx.x & 31;
    #pragma unroll
    for (int it = 0; it < 8; it++) {
        int dio = it * 8 + (threadIdx.x >> 5);  // warp-uniform
        int d2 = dio >> 1;
        float2 o;
        if (dio & 1) {
            o.x = sm[4096 + (d2 + p) * 64 + (p - d2 + 31)];
            o.y = sm[(d2 + p + 1) * 64 + (p - d2 + 32)];
        } else {
            o.x = sm[(d2 + p) * 64 + (p - d2 + 32)];
            o.y = sm[4096 + (d2 + p) * 64 + (p - d2 + 32)];
        }
        *(float2*)(op + (io0 + dio) * 256 + j0 + 2 * p) = o;
    }
}

// ---------------------------------------------------------------------------
extern "C" void kernel_launch(void* const* d_in, const int* in_sizes, int n_in,
                              void* d_out, int out_size)
{
    const float* y0 = (const float*)d_in[0];
    const float* y1 = (const float*)d_in[1];
    const float* y2 = (const float*)d_in[2];
    const float* y3 = (const float*)d_in[3];
    float* out = (float*)d_out;

    const dim3 blk(256);

    // Stage 1 (per, W=128): 512 planes of (128,128), tiles 32x64
    k_p1<<<dim3(2, 4, 512), blk>>>(y0, y1, y2, y3);
    k_p0<<<dim3(2, 4, 512), blk>>>(y1, y2);
    k_qprec2c<<<dim3(4, 2, 512), blk>>>();

    // Stage 2 (qper_col, W=256): 256 planes of (128,256), tiles 32x64
    k_q1<<<dim3(4, 4, 256), blk>>>();
    k_q0<<<dim3(4, 4, 256), blk>>>();
    k_qprec1r<<<dim3(4, 4, 256), blk>>>(out);
}

// round 11
// speedup vs baseline: 1.0122x; 1.0122x over previous
#include <cuda_runtime.h>

// ---------------------------------------------------------------------------
// Contourlet dfbrec4 reconstruction.
//   Stage 1: fbrec('2c','per')      on (8,64,128,128) -> X (8,64,128,256)
//   Stage 2: fbrec('1r','qper_col') on (8,32,128,256) -> out (8,32,256,256)
// ---------------------------------------------------------------------------

#define ISQ2 0.70710678118654752440f
#define SQ2  1.41421356237309504880f

// dfb filter taps as function-local constexpr -> FFMA immediates.
#define DECLARE_FILT() \
    constexpr float FILT[12] = { \
         0.0144f,  0.0272f,  0.0526f,  0.0972f,  0.193f,   0.63f, \
        -0.63f,   -0.193f,  -0.0972f, -0.0526f, -0.0272f, -0.0144f }

// Scratch (allocation-free rule: __device__ globals)
__device__ float g_p1[8 * 64 * 128 * 128];   // 32 MB
__device__ float g_p0[8 * 64 * 128 * 128];   // 32 MB
__device__ float g_X [8 * 64 * 128 * 256];   // 64 MB
__device__ float g_q1[8 * 32 * 128 * 256];   // 32 MB
__device__ float g_q0[8 * 32 * 128 * 256];   // 32 MB

#define EXT_S 84   // ext row stride (floats): mult of 4, 84 mod 32 = 20 -> vec conflict-free
#define TMP_S 68   // tmp row stride: mult of 4, 68 mod 32 = 4 -> vec conflict-free

// ---------------------------------------------------------------------------
// Separable 12-tap conv, 32x64 output tile, block = 256 threads (8 warps).
// halo -> smem(ext), H-pass via LDS.128 sliding window -> smem(tmp, STS.128),
// V-pass via column-pair LDS.64 -> float2 acc[4] (thread = 2 cols x 4 rows).
// Row wrap periodic mod 128; on wrap, column shifted by HSHIFT ('qper_col').
// ---------------------------------------------------------------------------
template <int W, int HSHIFT, int RC>
__device__ __forceinline__ void conv32x64(const float* __restrict__ plane,
                                          int r0, int c0,
                                          float* __restrict__ ext,   // 43*EXT_S
                                          float* __restrict__ tmp,   // 43*TMP_S
                                          float2 acc[4])
{
    DECLARE_FILT();
    const int tid  = threadIdx.x;
    const int lane = tid & 31;
    const int warp = tid >> 5;

    // ---- halo load: 43 rows x 75 cols; warp = row stripe, lane = col ----
    for (int er = warp; er < 43; er += 8) {
        int gr = r0 + er - RC;
        int cs = 0;
        if (gr < 0)        { gr += 128; cs = HSHIFT; }
        else if (gr >= 128){ gr -= 128; cs = HSHIFT; }
        const float* rowp = plane + gr * W;
        const int base = c0 - RC + cs;
        float* erow = ext + er * EXT_S;
        #pragma unroll
        for (int ec0 = 0; ec0 < 96; ec0 += 32) {
            int ec = ec0 + lane;
            if (ec < 75)
                erow[ec] = __ldg(rowp + ((base + ec) & (W - 1)));
        }
    }
    __syncthreads();

    // ---- horizontal pass: warp = 8-col strip, lane(+32) = row ----
    // 5 LDS.128 -> 19-value window -> 8 outputs -> 2 STS.128.
    {
        const int sb = warp << 3;
        #pragma unroll
        for (int half = 0; half < 2; half++) {
            int er = lane + half * 32;
            if (er < 43) {
                const float4* src = (const float4*)(ext + er * EXT_S + sb);
                float xx[20];
                #pragma unroll
                for (int q = 0; q < 5; q++) {
                    float4 v = src[q];
                    xx[4*q] = v.x; xx[4*q+1] = v.y; xx[4*q+2] = v.z; xx[4*q+3] = v.w;
                }
                float a[8] = {0.f,0.f,0.f,0.f,0.f,0.f,0.f,0.f};
                #pragma unroll
                for (int u = 0; u < 19; u++) {
                    #pragma unroll
                    for (int ss = 0; ss < 8; ss++) {
                        int k = u - ss;
                        if (k >= 0 && k < 12) a[ss] = fmaf(FILT[k], xx[u], a[ss]);
                    }
                }
                float4* dst = (float4*)(tmp + er * TMP_S + sb);
                dst[0] = make_float4(a[0], a[1], a[2], a[3]);
                dst[1] = make_float4(a[4], a[5], a[6], a[7]);
            }
        }
    }
    __syncthreads();

    // ---- vertical pass: thread = (col pair cp, 4-row strip rsb) ----
    const int cp  = tid & 31;
    const int rsb = tid >> 5;
    const float2* colp = (const float2*)tmp + rsb * (2 * TMP_S) + cp;
    #pragma unroll
    for (int ss = 0; ss < 4; ss++) { acc[ss].x = 0.f; acc[ss].y = 0.f; }
    #pragma unroll
    for (int u = 0; u < 15; u++) {
        float2 w = colp[u * (TMP_S / 2)];
        #pragma unroll
        for (int ss = 0; ss < 4; ss++) {
            int k = u - ss;
            if (k >= 0 && k < 12) {
                acc[ss].x = fmaf(FILT[k], w.x, acc[ss].x);
                acc[ss].y = fmaf(FILT[k], w.y, acc[ss].y);
            }
        }
    }
}

// ---------------------------------------------------------------------------
// Stage 1, step 1:  p1 = -isq2 * (Y1 + sep12(Y0, per, shift(0,0)))
//   Y0 = concat(y1, y2) on channels; Y1 = concat(y0, y3).
// grid (2, 4, 512)
// ---------------------------------------------------------------------------
__global__ __launch_bounds__(256) void k_p1(const float* __restrict__ y0,
                                            const float* __restrict__ y1,
                                            const float* __restrict__ y2,
                                            const float* __restrict__ y3)
{
    __shared__ float ext[43 * EXT_S];
    __shared__ float tmp[43 * TMP_S];
    const int z  = blockIdx.z;
    const int b  = z >> 6;
    const int ch = z & 63;
    const int half = (b << 5) + (ch & 31);
    const float* convp = (ch < 32 ? y1 : y2) + half * 16384;
    const float* combp = (ch < 32 ? y0 : y3) + half * 16384;
    float*       outp  = g_p1 + z * 16384;

    const int r0 = blockIdx.y << 5, c0 = blockIdx.x << 6;
    float2 acc[4];
    conv32x64<128, 0, 5>(convp, r0, c0, ext, tmp, acc);

    const int cp = threadIdx.x & 31, rsb = threadIdx.x >> 5;
    int base = (r0 + rsb * 4) * 128 + c0 + 2 * cp;
    #pragma unroll
    for (int i = 0; i < 4; i++, base += 128) {
        float2 cb = *(const float2*)(combp + base);
        float2 o;
        o.x = -ISQ2 * (cb.x + acc[i].x);
        o.y = -ISQ2 * (cb.y + acc[i].y);
        *(float2*)(outp + base) = o;
    }
}

// ---------------------------------------------------------------------------
// Stage 1, step 2:  p0 = sq2 * Y0 + sep12(p1, per, shift(1,1))
// ---------------------------------------------------------------------------
__global__ __launch_bounds__(256) void k_p0(const float* __restrict__ y1,
                                            const float* __restrict__ y2)
{
    __shared__ float ext[43 * EXT_S];
    __shared__ float tmp[43 * TMP_S];
    const int z  = blockIdx.z;
    const int b  = z >> 6;
    const int ch = z & 63;
    const int half = (b << 5) + (ch & 31);
    const float* convp = g_p1 + z * 16384;
    const float* combp = (ch < 32 ? y1 : y2) + half * 16384;
    float*       outp  = g_p0 + z * 16384;

    const int r0 = blockIdx.y << 5, c0 = blockIdx.x << 6;
    float2 acc[4];
    conv32x64<128, 0, 6>(convp, r0, c0, ext, tmp, acc);

    const int cp = threadIdx.x & 31, rsb = threadIdx.x >> 5;
    int base = (r0 + rsb * 4) * 128 + c0 + 2 * cp;
    #pragma unroll
    for (int i = 0; i < 4; i++, base += 128) {
        float2 cb = *(const float2*)(combp + base);
        float2 o;
        o.x = SQ2 * cb.x + acc[i].x;
        o.y = SQ2 * cb.y + acc[i].y;
        *(float2*)(outp + base) = o;
    }
}

// ---------------------------------------------------------------------------
// qprec '2c' (smem-staged, vectorized):
//   X[z][i][j], zc=(i+j) mod 256, t=zc>>1
//     even: X = p0[((i-j)/2)&127][((i+j)>>1)&127]
//     odd : X = p1[((i-j-1)/2)&127][((i+j-1)>>1)&127]
// Load: float4 (T0 mult of 32 -> aligned; col (T0+4l)&127 stays 4-aligned).
// Gather: dj-pairs, di warp-uniform -> no divergence, STG.64.
// grid (4, 2, 512), block 256
// ---------------------------------------------------------------------------
__global__ __launch_bounds__(256) void k_qprec2c()
{
    __shared__ float sm[2 * 64 * 64];
    const int z  = blockIdx.z;
    const int i0 = blockIdx.y << 6;
    const int j0 = blockIdx.x << 6;
    const float* p0 = g_p0 + z * 16384;
    const float* p1 = g_p1 + z * 16384;

    const int T0  = ((i0 + j0) >> 1) & 127;
    const int ihj = (i0 - j0) >> 1;
    const int D0  = (ihj - 31) & 127;        // sm0 row base
    const int D1  = (ihj - 32) & 127;        // sm1 row base

    const int l  = threadIdx.x & 15;
    const int u0 = threadIdx.x >> 4;
    #pragma unroll
    for (int it = 0; it < 4; it++) {
        int v   = u0 + it * 16;
        int col = (T0 + 4 * l) & 127;
        float4 a = *(const float4*)(p0 + (((D0 + v) & 127) << 7) + col);
        float4 b = *(const float4*)(p1 + (((D1 + v) & 127) << 7) + col);
        *(float4*)(sm + v * 64 + 4 * l)        = a;
        *(float4*)(sm + 4096 + v * 64 + 4 * l) = b;
    }
    __syncthreads();

    float* Xp = g_X + z * 32768;
    const int p = threadIdx.x & 31;
    #pragma unroll
    for (int it = 0; it < 8; it++) {
        int di = it * 8 + (threadIdx.x >> 5);   // warp-uniform
        int d2 = di >> 1;
        float2 o;
        if (di & 1) {
            o.x = sm[4096 + (d2 - p + 32) * 64 + (d2 + p)];
            o.y = sm[(d2 - p + 31) * 64 + (d2 + p + 1)];
        } else {
            int off = (d2 - p + 31) * 64 + (d2 + p);
            o.x = sm[off];
            o.y = sm[4096 + off];
        }
        *(float2*)(Xp + (i0 + di) * 256 + j0 + 2 * p) = o;
    }
}

// ---------------------------------------------------------------------------
// Stage 2, step 1:  q1 = -isq2 * (x1 + sep12(x0, qper_col, shift(0,0)))
//   x0 = X[:, :32], x1 = X[:, 32:].  W = 256, half-shift = 128.
// grid (4, 4, 256)
// ---------------------------------------------------------------------------
__global__ __launch_bounds__(256) void k_q1()
{
    __shared__ float ext[43 * EXT_S];
    __shared__ float tmp[43 * TMP_S];
    const int z  = blockIdx.z;
    const int b  = z >> 5;
    const int ch = z & 31;
    const float* convp = g_X + (b * 64 + ch) * 32768;
    const float* combp = g_X + (b * 64 + 32 + ch) * 32768;
    float*       outp  = g_q1 + z * 32768;

    const int r0 = blockIdx.y << 5, c0 = blockIdx.x << 6;
    float2 acc[4];
    conv32x64<256, 128, 5>(convp, r0, c0, ext, tmp, acc);

    const int cp = threadIdx.x & 31, rsb = threadIdx.x >> 5;
    int base = (r0 + rsb * 4) * 256 + c0 + 2 * cp;
    #pragma unroll
    for (int i = 0; i < 4; i++, base += 256) {
        float2 cb = *(const float2*)(combp + base);
        float2 o;
        o.x = -ISQ2 * (cb.x + acc[i].x);
        o.y = -ISQ2 * (cb.y + acc[i].y);
        *(float2*)(outp + base) = o;
    }
}

// ---------------------------------------------------------------------------
// Stage 2, step 2:  q0 = sq2 * x0 + sep12(q1, qper_col, shift(1,1))
// ---------------------------------------------------------------------------
__global__ __launch_bounds__(256) void k_q0()
{
    __shared__ float ext[43 * EXT_S];
    __shared__ float tmp[43 * TMP_S];
    const int z  = blockIdx.z;
    const int b  = z >> 5;
    const int ch = z & 31;
    const float* convp = g_q1 + z * 32768;
    const float* combp = g_X + (b * 64 + ch) * 32768;
    float*       outp  = g_q0 + z * 32768;

    const int r0 = blockIdx.y << 5, c0 = blockIdx.x << 6;
    float2 acc[4];
    conv32x64<256, 128, 6>(convp, r0, c0, ext, tmp, acc);

    const int cp = threadIdx.x & 31, rsb = threadIdx.x >> 5;
    int base = (r0 + rsb * 4) * 256 + c0 + 2 * cp;
    #pragma unroll
    for (int i = 0; i < 4; i++, base += 256) {
        float2 cb = *(const float2*)(combp + base);
        float2 o;
        o.x = SQ2 * cb.x + acc[i].x;
        o.y = SQ2 * cb.y + acc[i].y;
        *(float2*)(outp + base) = o;
    }
}

// ---------------------------------------------------------------------------
// qprec '1r' (smem-staged, vectorized, wrap-correct):
//   out[z][io][j]: zr = (io+j) mod 256, t = zr>>1
//     even: out = q0[t][(j-t)&255];  odd: out = q1[t][(j-1-t)&255]
// Staged row u holds cols (chb-32+w128(u) + l)&255, l in [0,64); base mult of
// 32 -> float4 loads. w128(u) = 128*(S0+2u >= 256) handles the mod-256 wrap.
// Gather (l offsets re-derived for the -32 base):
//   even s: l = (dj-dio)/2   + 32;  odd s: l = (dj-dio-1)/2 + 32.
// grid (4, 4, 256), block 256
// ---------------------------------------------------------------------------
__global__ __launch_bounds__(256) void k_qprec1r(float* __restrict__ out)
{
    __shared__ float sm[2 * 64 * 64];
    const int z   = blockIdx.z;
    const int io0 = blockIdx.y << 6;
    const int j0  = blockIdx.x << 6;
    const float* q0 = g_q0 + z * 32768;
    const float* q1 = g_q1 + z * 32768;

    const int S0  = io0 + j0;
    const int T0  = (S0 >> 1) & 127;
    const int chb = (j0 - io0) >> 1;

    const int l  = threadIdx.x & 15;
    const int u0 = threadIdx.x >> 4;
    #pragma unroll
    for (int it = 0; it < 4; it++) {
        int u    = u0 + it * 16;
        int row  = ((T0 + u) & 127) << 8;
        int w128 = (S0 + 2 * u >= 256) ? 128 : 0;
        int col  = (chb - 32 + w128 + 4 * l) & 255;
        float4 a = *(const float4*)(q0 + row + col);
        float4 b = *(const float4*)(q1 + row + col);
        *(float4*)(sm + u * 64 + 4 * l)        = a;
        *(float4*)(sm + 4096 + u * 64 + 4 * l) = b;
    }
    __syncthreads();

    float* op = out + z * 65536;
    const int p = threadIdx.x & 31;
    #pragma unroll
    for (int it = 0; it < 8; it++) {
        int dio = it * 8 + (threadIdx.x >> 5);  // warp-uniform
        int d2 = dio >> 1;
        float2 o;
        if (dio & 1) {
            o.x = sm[4096 + (d2 + p) * 64 + (p - d2 + 31)];
            o.y = sm[(d2 + p + 1) * 64 + (p - d2 + 32)];
        } else {
            o.x = sm[(d2 + p) * 64 + (p - d2 + 32)];
            o.y = sm[4096 + (d2 + p) * 64 + (p - d2 + 32)];
        }
        *(float2*)(op + (io0 + dio) * 256 + j0 + 2 * p) = o;
    }
}

// ---------------------------------------------------------------------------
extern "C" void kernel_launch(void* const* d_in, const int* in_sizes, int n_in,
                              void* d_out, int out_size)
{
    const float* y0 = (const float*)d_in[0];
    const float* y1 = (const float*)d_in[1];
    const float* y2 = (const float*)d_in[2];
    const float* y3 = (const float*)d_in[3];
    float* out = (float*)d_out;

    const dim3 blk(256);

    // Stage 1 (per, W=128): 512 planes of (128,128), tiles 32x64
    k_p1<<<dim3(2, 4, 512), blk>>>(y0, y1, y2, y3);
    k_p0<<<dim3(2, 4, 512), blk>>>(y1, y2);
    k_qprec2c<<<dim3(4, 2, 512), blk>>>();

    // Stage 2 (qper_col, W=256): 256 planes of (128,256), tiles 32x64
    k_q1<<<dim3(4, 4, 256), blk>>>();
    k_q0<<<dim3(4, 4, 256), blk>>>();
    k_qprec1r<<<dim3(4, 4, 256), blk>>>(out);
}